// round 1
// baseline (speedup 1.0000x reference)
#include <cuda_runtime.h>
#include <math.h>

#define NB 4096      // boxes
#define NE 32768     // edges
#define OD 2048      // obj_dim
#define FD 2432      // feats_dim

// ---------------- static scratch (no cudaMalloc allowed) ----------------
__device__ float g_box_att[(size_t)NB * OD];   // box_feats @ Wa_box        32 MB
__device__ float g_rel_att[(size_t)NE * OD];   // rel_feats @ Wa_rel       256 MB
__device__ float g_logit[2 * NE];              // [s | o]
__device__ float g_alpha[2 * NE];              // exp(logit - max) (raw)
__device__ float g_nmax[2 * NB];
__device__ float g_denom[2 * NB];
__device__ float g_salpha[2 * NB];             // sum of alphas per node = d/(d+1e-9)
__device__ float g_wsum[2ull * NB * FD];       // weighted rel sums [s|o]   80 MB
__device__ float g_acc[(size_t)NB * OD];       // final accumulation        32 MB

// ---------------- init ----------------
__global__ void init_kernel() {
    size_t idx = (size_t)blockIdx.x * blockDim.x + threadIdx.x;
    size_t stride = (size_t)gridDim.x * blockDim.x;
    for (size_t i = idx; i < 2ull * NB * FD; i += stride) g_wsum[i] = 0.f;
    for (size_t i = idx; i < 2 * NB; i += stride) {
        g_denom[i] = 0.f;
        g_nmax[i] = -INFINITY;
    }
}

// ---------------- generic fp32 GEMM: Cout = [relu]( A[M,K] @ B[K,N] (+Cin) ) ----------------
#define BM 128
#define BN 128
#define BKK 8
#define TM 8
#define TN 8

__global__ __launch_bounds__(256, 2)
void gemm_kernel(const float* __restrict__ A, const float* __restrict__ B,
                 const float* __restrict__ Cin, float* __restrict__ Cout,
                 int M, int N, int K, int do_relu) {
    __shared__ float As[BKK][BM];
    __shared__ float Bs[BKK][BN];

    const int tid = threadIdx.x;
    const int tx = tid % 16;       // N direction
    const int ty = tid / 16;       // M direction
    const int bx = blockIdx.x;     // N tile
    const int by = blockIdx.y;     // M tile

    // A tile load: 128 rows x 8 k -> each thread one float4 along K
    const int a_row  = tid >> 1;            // 0..127
    const int a_col4 = (tid & 1) * 4;       // 0 or 4
    // B tile load: 8 rows x 128 n -> each thread one float4 along N
    const int b_row  = tid >> 5;            // 0..7
    const int b_col4 = (tid & 31) * 4;      // 0..124

    const float* A_blk = A + (size_t)by * BM * K;
    const float* B_blk = B + (size_t)bx * BN;

    float acc[TM][TN];
    #pragma unroll
    for (int i = 0; i < TM; i++)
        #pragma unroll
        for (int j = 0; j < TN; j++) acc[i][j] = 0.f;

    for (int k0 = 0; k0 < K; k0 += BKK) {
        float4 av = *(const float4*)(A_blk + (size_t)a_row * K + k0 + a_col4);
        As[a_col4 + 0][a_row] = av.x;
        As[a_col4 + 1][a_row] = av.y;
        As[a_col4 + 2][a_row] = av.z;
        As[a_col4 + 3][a_row] = av.w;
        float4 bv = *(const float4*)(B_blk + (size_t)(k0 + b_row) * N + b_col4);
        *(float4*)&Bs[b_row][b_col4] = bv;
        __syncthreads();

        #pragma unroll
        for (int kk = 0; kk < BKK; kk++) {
            float4 a0 = *(const float4*)&As[kk][ty * TM];
            float4 a1 = *(const float4*)&As[kk][ty * TM + 4];
            float4 b0 = *(const float4*)&Bs[kk][tx * TN];
            float4 b1 = *(const float4*)&Bs[kk][tx * TN + 4];
            float a[TM] = {a0.x, a0.y, a0.z, a0.w, a1.x, a1.y, a1.z, a1.w};
            float b[TN] = {b0.x, b0.y, b0.z, b0.w, b1.x, b1.y, b1.z, b1.w};
            #pragma unroll
            for (int i = 0; i < TM; i++)
                #pragma unroll
                for (int j = 0; j < TN; j++)
                    acc[i][j] = fmaf(a[i], b[j], acc[i][j]);
        }
        __syncthreads();
    }

    #pragma unroll
    for (int i = 0; i < TM; i++) {
        size_t r = (size_t)by * BM + ty * TM + i;
        #pragma unroll
        for (int j = 0; j < TN; j += 4) {
            size_t c = (size_t)bx * BN + tx * TN + j;
            float4 v = make_float4(acc[i][j], acc[i][j + 1], acc[i][j + 2], acc[i][j + 3]);
            if (Cin) {
                float4 ci = *(const float4*)(Cin + r * N + c);
                v.x += ci.x; v.y += ci.y; v.z += ci.z; v.w += ci.w;
            }
            if (do_relu) {
                v.x = fmaxf(v.x, 0.f); v.y = fmaxf(v.y, 0.f);
                v.z = fmaxf(v.z, 0.f); v.w = fmaxf(v.w, 0.f);
            }
            *(float4*)(Cout + r * N + c) = v;
        }
    }
}

// ---------------- logits: per edge, dot(relu(rel_att + box_att[idx] + b_a1), Wa2) ----------------
__global__ __launch_bounds__(256)
void logit_kernel(const int* __restrict__ sub, const int* __restrict__ obj,
                  const float* __restrict__ b_a1, const float* __restrict__ Wa2,
                  const float* __restrict__ b_a2) {
    const int e = blockIdx.x;
    const int tid = threadIdx.x;
    const int s = sub[e], o = obj[e];

    const float4* ra = (const float4*)(g_rel_att + (size_t)e * OD);
    const float4* bs = (const float4*)(g_box_att + (size_t)s * OD);
    const float4* bo = (const float4*)(g_box_att + (size_t)o * OD);
    const float4* bb = (const float4*)b_a1;
    const float4* w  = (const float4*)Wa2;

    float ps = 0.f, po = 0.f;
    for (int i = tid; i < OD / 4; i += blockDim.x) {
        float4 r = ra[i], b1 = bs[i], b2 = bo[i], bi = bb[i], wv = w[i];
        ps = fmaf(fmaxf(r.x + b1.x + bi.x, 0.f), wv.x, ps);
        ps = fmaf(fmaxf(r.y + b1.y + bi.y, 0.f), wv.y, ps);
        ps = fmaf(fmaxf(r.z + b1.z + bi.z, 0.f), wv.z, ps);
        ps = fmaf(fmaxf(r.w + b1.w + bi.w, 0.f), wv.w, ps);
        po = fmaf(fmaxf(r.x + b2.x + bi.x, 0.f), wv.x, po);
        po = fmaf(fmaxf(r.y + b2.y + bi.y, 0.f), wv.y, po);
        po = fmaf(fmaxf(r.z + b2.z + bi.z, 0.f), wv.z, po);
        po = fmaf(fmaxf(r.w + b2.w + bi.w, 0.f), wv.w, po);
    }
    // block reduce
    __shared__ float red[2][8];
    #pragma unroll
    for (int off = 16; off > 0; off >>= 1) {
        ps += __shfl_down_sync(0xffffffffu, ps, off);
        po += __shfl_down_sync(0xffffffffu, po, off);
    }
    if ((tid & 31) == 0) { red[0][tid >> 5] = ps; red[1][tid >> 5] = po; }
    __syncthreads();
    if (tid == 0) {
        float a = 0.f, b = 0.f;
        #pragma unroll
        for (int wi = 0; wi < 8; wi++) { a += red[0][wi]; b += red[1][wi]; }
        float ba2 = b_a2[0];
        g_logit[e]      = a + ba2;
        g_logit[NE + e] = b + ba2;
    }
}

// ---------------- segment max via float atomics ----------------
__device__ __forceinline__ void atomicMaxF(float* addr, float v) {
    if (v >= 0.f) atomicMax((int*)addr, __float_as_int(v));
    else          atomicMin((unsigned int*)addr, __float_as_uint(v));
}

__global__ void segmax_kernel(const int* __restrict__ sub, const int* __restrict__ obj) {
    int e = blockIdx.x * blockDim.x + threadIdx.x;
    if (e >= NE) return;
    atomicMaxF(&g_nmax[sub[e]], g_logit[e]);
    atomicMaxF(&g_nmax[NB + obj[e]], g_logit[NE + e]);
}

__global__ void expsum_kernel(const int* __restrict__ sub, const int* __restrict__ obj) {
    int e = blockIdx.x * blockDim.x + threadIdx.x;
    if (e >= NE) return;
    int s = sub[e], o = obj[e];
    float es = expf(g_logit[e] - g_nmax[s]);
    float eo = expf(g_logit[NE + e] - g_nmax[NB + o]);
    g_alpha[e] = es;
    g_alpha[NE + e] = eo;
    atomicAdd(&g_denom[s], es);
    atomicAdd(&g_denom[NB + o], eo);
}

__global__ void salpha_kernel() {
    int i = blockIdx.x * blockDim.x + threadIdx.x;
    if (i >= 2 * NB) return;
    float d = g_denom[i];
    g_salpha[i] = d / (d + 1e-9f);   // 0 for empty nodes
}

// ---------------- weighted scatter: wsum[node] += alpha * rel_feats[e] ----------------
__global__ __launch_bounds__(256)
void scatter_kernel(const float* __restrict__ rel, const int* __restrict__ sub,
                    const int* __restrict__ obj) {
    const int e = blockIdx.x;
    const int tid = threadIdx.x;
    const int s = sub[e], o = obj[e];
    const float as = g_alpha[e] / (g_denom[s] + 1e-9f);
    const float ao = g_alpha[NE + e] / (g_denom[NB + o] + 1e-9f);

    const float4* r = (const float4*)(rel + (size_t)e * FD);
    float* ws = g_wsum + (size_t)s * FD;
    float* wo = g_wsum + ((size_t)NB + o) * FD;
    for (int i = tid; i < FD / 4; i += blockDim.x) {
        float4 v = r[i];
        int c = i * 4;
        atomicAdd(&ws[c + 0], as * v.x);
        atomicAdd(&ws[c + 1], as * v.y);
        atomicAdd(&ws[c + 2], as * v.z);
        atomicAdd(&ws[c + 3], as * v.w);
        atomicAdd(&wo[c + 0], ao * v.x);
        atomicAdd(&wo[c + 1], ao * v.y);
        atomicAdd(&wo[c + 2], ao * v.z);
        atomicAdd(&wo[c + 3], ao * v.w);
    }
}

// ---------------- acc init with biases: b_box + sa_s*b_sub + sa_o*b_obj ----------------
__global__ void biasinit_kernel(const float* __restrict__ b_box,
                                const float* __restrict__ b_sub,
                                const float* __restrict__ b_obj) {
    size_t idx = (size_t)blockIdx.x * blockDim.x + threadIdx.x;
    if (idx >= (size_t)NB * OD) return;
    int i = (int)(idx / OD);
    int n = (int)(idx % OD);
    g_acc[idx] = b_box[n] + g_salpha[i] * b_sub[n] + g_salpha[NB + i] * b_obj[n];
}

// ---------------- launch ----------------
extern "C" void kernel_launch(void* const* d_in, const int* in_sizes, int n_in,
                              void* d_out, int out_size) {
    const float* box_feats = (const float*)d_in[0];
    const float* rel_feats = (const float*)d_in[1];
    const int*   edge_sub  = (const int*)d_in[2];
    const int*   edge_obj  = (const int*)d_in[3];
    const float* W_box  = (const float*)d_in[4];
    const float* b_box  = (const float*)d_in[5];
    const float* W_sub  = (const float*)d_in[6];
    const float* b_sub  = (const float*)d_in[7];
    const float* W_obj  = (const float*)d_in[8];
    const float* b_obj  = (const float*)d_in[9];
    const float* Wa_box = (const float*)d_in[10];
    const float* Wa_rel = (const float*)d_in[11];
    const float* b_a1   = (const float*)d_in[12];
    const float* Wa2    = (const float*)d_in[13];
    const float* b_a2   = (const float*)d_in[14];
    float* out = (float*)d_out;

    float *box_att, *rel_att, *wsum, *acc;
    cudaGetSymbolAddress((void**)&box_att, g_box_att);
    cudaGetSymbolAddress((void**)&rel_att, g_rel_att);
    cudaGetSymbolAddress((void**)&wsum, g_wsum);
    cudaGetSymbolAddress((void**)&acc, g_acc);

    init_kernel<<<2048, 256>>>();

    // box_att = box_feats @ Wa_box
    gemm_kernel<<<dim3(OD / BN, NB / BM), 256>>>(box_feats, Wa_box, nullptr, box_att,
                                                 NB, OD, OD, 0);
    // rel_att = rel_feats @ Wa_rel    (dominant GEMM)
    gemm_kernel<<<dim3(OD / BN, NE / BM), 256>>>(rel_feats, Wa_rel, nullptr, rel_att,
                                                 NE, OD, FD, 0);

    logit_kernel<<<NE, 256>>>(edge_sub, edge_obj, b_a1, Wa2, b_a2);
    segmax_kernel<<<(NE + 255) / 256, 256>>>(edge_sub, edge_obj);
    expsum_kernel<<<(NE + 255) / 256, 256>>>(edge_sub, edge_obj);
    salpha_kernel<<<(2 * NB + 255) / 256, 256>>>();
    scatter_kernel<<<NE, 256>>>(rel_feats, edge_sub, edge_obj);

    biasinit_kernel<<<(int)(((size_t)NB * OD + 255) / 256), 256>>>(b_box, b_sub, b_obj);

    // acc += box_feats @ W_box ; acc += wsum_s @ W_sub ; out = relu(acc + wsum_o @ W_obj)
    gemm_kernel<<<dim3(OD / BN, NB / BM), 256>>>(box_feats, W_box, acc, acc,
                                                 NB, OD, OD, 0);
    gemm_kernel<<<dim3(OD / BN, NB / BM), 256>>>(wsum, W_sub, acc, acc,
                                                 NB, OD, FD, 0);
    gemm_kernel<<<dim3(OD / BN, NB / BM), 256>>>(wsum + (size_t)NB * FD, W_obj, acc, out,
                                                 NB, OD, FD, 1);
}

// round 4
// speedup vs baseline: 2.9925x; 2.9925x over previous
#include <cuda_runtime.h>
#include <cuda_bf16.h>
#include <math.h>
#include <stdint.h>

#define NB 4096      // boxes
#define NE 32768     // edges
#define OD 2048      // obj_dim
#define FD 2432      // feats_dim

// ---------------- static scratch (no cudaMalloc allowed) ----------------
__device__ float g_box_att[(size_t)NB * OD];   // box_feats @ Wa_box        32 MB
__device__ float g_rel_att[(size_t)NE * OD];   // rel_feats @ Wa_rel       256 MB
__device__ float g_logit[2 * NE];
__device__ float g_alpha[2 * NE];
__device__ float g_nmax[2 * NB];
__device__ float g_denom[2 * NB];
__device__ float g_salpha[2 * NB];
__device__ float g_wsum[2ull * NB * FD];       // weighted rel sums [s|o]   80 MB
__device__ float g_acc[(size_t)NB * OD];       // final accumulation        32 MB

// bf16 hi/lo split buffers
__device__ __nv_bfloat16 g_relh[(size_t)NE * FD], g_rell[(size_t)NE * FD];
__device__ __nv_bfloat16 g_boxh[(size_t)NB * OD], g_boxl[(size_t)NB * OD];
__device__ __nv_bfloat16 g_wsh[2ull * NB * FD],  g_wsl[2ull * NB * FD];
__device__ __nv_bfloat16 g_Wabh[(size_t)OD * OD], g_Wabl[(size_t)OD * OD];
__device__ __nv_bfloat16 g_Warh[(size_t)FD * OD], g_Warl[(size_t)FD * OD];
__device__ __nv_bfloat16 g_Wbh[(size_t)OD * OD],  g_Wbl[(size_t)OD * OD];
__device__ __nv_bfloat16 g_Wsh[(size_t)FD * OD],  g_Wsl[(size_t)FD * OD];
__device__ __nv_bfloat16 g_Woh[(size_t)FD * OD],  g_Wol[(size_t)FD * OD];

// ---------------- init ----------------
__global__ void init_kernel() {
    size_t idx = (size_t)blockIdx.x * blockDim.x + threadIdx.x;
    size_t stride = (size_t)gridDim.x * blockDim.x;
    for (size_t i = idx; i < 2ull * NB * FD; i += stride) g_wsum[i] = 0.f;
    for (size_t i = idx; i < 2 * NB; i += stride) {
        g_denom[i] = 0.f;
        g_nmax[i] = -INFINITY;
    }
}

// ---------------- fp32 -> bf16 hi/lo split ----------------
__global__ void split_kernel(const float* __restrict__ src,
                             __nv_bfloat16* __restrict__ hi,
                             __nv_bfloat16* __restrict__ lo, long n) {
    long i = ((long)blockIdx.x * blockDim.x + threadIdx.x) * 4;
    if (i >= n) return;
    float4 v = *(const float4*)(src + i);
    __nv_bfloat16 h[4], l[4];
    h[0] = __float2bfloat16_rn(v.x); l[0] = __float2bfloat16_rn(v.x - __bfloat162float(h[0]));
    h[1] = __float2bfloat16_rn(v.y); l[1] = __float2bfloat16_rn(v.y - __bfloat162float(h[1]));
    h[2] = __float2bfloat16_rn(v.z); l[2] = __float2bfloat16_rn(v.z - __bfloat162float(h[2]));
    h[3] = __float2bfloat16_rn(v.w); l[3] = __float2bfloat16_rn(v.w - __bfloat162float(h[3]));
    *(uint2*)(hi + i) = *(uint2*)h;
    *(uint2*)(lo + i) = *(uint2*)l;
}

// ---------------- MMA helpers ----------------
__device__ __forceinline__ uint32_t sptr(const void* p) {
    return (uint32_t)__cvta_generic_to_shared(p);
}
__device__ __forceinline__ void ldm4(uint32_t* r, uint32_t a) {
    asm volatile("ldmatrix.sync.aligned.m8n8.x4.shared.b16 {%0,%1,%2,%3}, [%4];"
        : "=r"(r[0]), "=r"(r[1]), "=r"(r[2]), "=r"(r[3]) : "r"(a));
}
__device__ __forceinline__ void ldm4t(uint32_t* r, uint32_t a) {
    asm volatile("ldmatrix.sync.aligned.m8n8.x4.trans.shared.b16 {%0,%1,%2,%3}, [%4];"
        : "=r"(r[0]), "=r"(r[1]), "=r"(r[2]), "=r"(r[3]) : "r"(a));
}
__device__ __forceinline__ void mma16816(float* c, const uint32_t* a, const uint32_t* b) {
    asm volatile("mma.sync.aligned.m16n8k16.row.col.f32.bf16.bf16.f32 "
        "{%0,%1,%2,%3}, {%4,%5,%6,%7}, {%8,%9}, {%0,%1,%2,%3};"
        : "+f"(c[0]), "+f"(c[1]), "+f"(c[2]), "+f"(c[3])
        : "r"(a[0]), "r"(a[1]), "r"(a[2]), "r"(a[3]), "r"(b[0]), "r"(b[1]));
}

// ---------------- bf16 hi/lo tensor-core GEMM ----------------
// Cout[M,N] = [relu]( (Ahi+Alo)[M,K] @ (Bhi+Blo)[K,N] (+Cin) ), fp32 accum.
// CTA tile 128x128, BK=32, 8 warps (2x4), warp tile 64x32.
#define LDA 40
#define LDB 136

__global__ __launch_bounds__(256, 2)
void mma_gemm(const __nv_bfloat16* __restrict__ Ahi, const __nv_bfloat16* __restrict__ Alo,
              const __nv_bfloat16* __restrict__ Bhi, const __nv_bfloat16* __restrict__ Blo,
              const float* __restrict__ Cin, float* __restrict__ Cout,
              int M, int N, int K, int do_relu) {
    __shared__ __nv_bfloat16 sAh[128 * LDA], sAl[128 * LDA];
    __shared__ __nv_bfloat16 sBh[32 * LDB],  sBl[32 * LDB];

    const int tid  = threadIdx.x;
    const int lane = tid & 31;
    const int wid  = tid >> 5;
    const int wm   = wid & 1;       // 0..1  -> 64-row slab
    const int wn   = wid >> 1;      // 0..3  -> 32-col slab
    const int bm   = blockIdx.y * 128;
    const int bn   = blockIdx.x * 128;

    float acc[4][4][4];
    #pragma unroll
    for (int i = 0; i < 4; i++)
        #pragma unroll
        for (int j = 0; j < 4; j++)
            #pragma unroll
            for (int q = 0; q < 4; q++) acc[i][j][q] = 0.f;

    for (int k0 = 0; k0 < K; k0 += 32) {
        #pragma unroll
        for (int p = 0; p < 2; p++) {
            int u  = tid + p * 256;
            int r  = u >> 2,  cg = (u & 3) << 3;     // A: 128 rows x 32 cols
            int rb = u >> 4,  cb = (u & 15) << 3;    // B: 32 rows x 128 cols
            *(uint4*)&sAh[r * LDA + cg]  = *(const uint4*)(Ahi + (size_t)(bm + r) * K + k0 + cg);
            *(uint4*)&sAl[r * LDA + cg]  = *(const uint4*)(Alo + (size_t)(bm + r) * K + k0 + cg);
            *(uint4*)&sBh[rb * LDB + cb] = *(const uint4*)(Bhi + (size_t)(k0 + rb) * N + bn + cb);
            *(uint4*)&sBl[rb * LDB + cb] = *(const uint4*)(Blo + (size_t)(k0 + rb) * N + bn + cb);
        }
        __syncthreads();

        #pragma unroll
        for (int ks = 0; ks < 32; ks += 16) {
            uint32_t bh[2][4], bl[2][4];
            #pragma unroll
            for (int nh = 0; nh < 2; nh++) {
                int rr = ks + (lane & 15);
                int cc = wn * 32 + nh * 16 + ((lane >> 4) << 3);
                ldm4t(bh[nh], sptr(&sBh[rr * LDB + cc]));
                ldm4t(bl[nh], sptr(&sBl[rr * LDB + cc]));
            }
            #pragma unroll
            for (int mt = 0; mt < 4; mt++) {
                uint32_t ah[4], al[4];
                int ar = wm * 64 + mt * 16 + (lane & 15);
                int ac = ks + ((lane >> 4) << 3);
                ldm4(ah, sptr(&sAh[ar * LDA + ac]));
                ldm4(al, sptr(&sAl[ar * LDA + ac]));
                #pragma unroll
                for (int nt = 0; nt < 4; nt++) {
                    const uint32_t* ph = &bh[nt >> 1][(nt & 1) * 2];
                    const uint32_t* pl = &bl[nt >> 1][(nt & 1) * 2];
                    mma16816(acc[mt][nt], ah, ph);   // hi*hi
                    mma16816(acc[mt][nt], ah, pl);   // hi*lo
                    mma16816(acc[mt][nt], al, ph);   // lo*hi
                }
            }
        }
        __syncthreads();
    }

    // epilogue
    const int r0 = bm + wm * 64;
    const int c0 = bn + wn * 32;
    #pragma unroll
    for (int mt = 0; mt < 4; mt++) {
        #pragma unroll
        for (int nt = 0; nt < 4; nt++) {
            int row = r0 + mt * 16 + (lane >> 2);
            int col = c0 + nt * 8 + ((lane & 3) << 1);
            float2 v01 = make_float2(acc[mt][nt][0], acc[mt][nt][1]);
            float2 v23 = make_float2(acc[mt][nt][2], acc[mt][nt][3]);
            if (Cin) {
                float2 c1 = *(const float2*)(Cin + (size_t)row * N + col);
                float2 c2 = *(const float2*)(Cin + (size_t)(row + 8) * N + col);
                v01.x += c1.x; v01.y += c1.y;
                v23.x += c2.x; v23.y += c2.y;
            }
            if (do_relu) {
                v01.x = fmaxf(v01.x, 0.f); v01.y = fmaxf(v01.y, 0.f);
                v23.x = fmaxf(v23.x, 0.f); v23.y = fmaxf(v23.y, 0.f);
            }
            *(float2*)(Cout + (size_t)row * N + col)       = v01;
            *(float2*)(Cout + (size_t)(row + 8) * N + col) = v23;
        }
    }
}

// ---------------- logits ----------------
__global__ __launch_bounds__(256)
void logit_kernel(const int* __restrict__ sub, const int* __restrict__ obj,
                  const float* __restrict__ b_a1, const float* __restrict__ Wa2,
                  const float* __restrict__ b_a2) {
    const int e = blockIdx.x;
    const int tid = threadIdx.x;
    const int s = sub[e], o = obj[e];

    const float4* ra = (const float4*)(g_rel_att + (size_t)e * OD);
    const float4* bs = (const float4*)(g_box_att + (size_t)s * OD);
    const float4* bo = (const float4*)(g_box_att + (size_t)o * OD);
    const float4* bb = (const float4*)b_a1;
    const float4* w  = (const float4*)Wa2;

    float ps = 0.f, po = 0.f;
    for (int i = tid; i < OD / 4; i += blockDim.x) {
        float4 r = ra[i], b1 = bs[i], b2 = bo[i], bi = bb[i], wv = w[i];
        ps = fmaf(fmaxf(r.x + b1.x + bi.x, 0.f), wv.x, ps);
        ps = fmaf(fmaxf(r.y + b1.y + bi.y, 0.f), wv.y, ps);
        ps = fmaf(fmaxf(r.z + b1.z + bi.z, 0.f), wv.z, ps);
        ps = fmaf(fmaxf(r.w + b1.w + bi.w, 0.f), wv.w, ps);
        po = fmaf(fmaxf(r.x + b2.x + bi.x, 0.f), wv.x, po);
        po = fmaf(fmaxf(r.y + b2.y + bi.y, 0.f), wv.y, po);
        po = fmaf(fmaxf(r.z + b2.z + bi.z, 0.f), wv.z, po);
        po = fmaf(fmaxf(r.w + b2.w + bi.w, 0.f), wv.w, po);
    }
    __shared__ float red[2][8];
    #pragma unroll
    for (int off = 16; off > 0; off >>= 1) {
        ps += __shfl_down_sync(0xffffffffu, ps, off);
        po += __shfl_down_sync(0xffffffffu, po, off);
    }
    if ((tid & 31) == 0) { red[0][tid >> 5] = ps; red[1][tid >> 5] = po; }
    __syncthreads();
    if (tid == 0) {
        float a = 0.f, b = 0.f;
        #pragma unroll
        for (int wi = 0; wi < 8; wi++) { a += red[0][wi]; b += red[1][wi]; }
        float ba2 = b_a2[0];
        g_logit[e]      = a + ba2;
        g_logit[NE + e] = b + ba2;
    }
}

// ---------------- segment softmax pieces ----------------
__device__ __forceinline__ void atomicMaxF(float* addr, float v) {
    if (v >= 0.f) atomicMax((int*)addr, __float_as_int(v));
    else          atomicMin((unsigned int*)addr, __float_as_uint(v));
}

__global__ void segmax_kernel(const int* __restrict__ sub, const int* __restrict__ obj) {
    int e = blockIdx.x * blockDim.x + threadIdx.x;
    if (e >= NE) return;
    atomicMaxF(&g_nmax[sub[e]], g_logit[e]);
    atomicMaxF(&g_nmax[NB + obj[e]], g_logit[NE + e]);
}

__global__ void expsum_kernel(const int* __restrict__ sub, const int* __restrict__ obj) {
    int e = blockIdx.x * blockDim.x + threadIdx.x;
    if (e >= NE) return;
    int s = sub[e], o = obj[e];
    float es = expf(g_logit[e] - g_nmax[s]);
    float eo = expf(g_logit[NE + e] - g_nmax[NB + o]);
    g_alpha[e] = es;
    g_alpha[NE + e] = eo;
    atomicAdd(&g_denom[s], es);
    atomicAdd(&g_denom[NB + o], eo);
}

__global__ void salpha_kernel() {
    int i = blockIdx.x * blockDim.x + threadIdx.x;
    if (i >= 2 * NB) return;
    float d = g_denom[i];
    g_salpha[i] = d / (d + 1e-9f);
}

// ---------------- weighted scatter ----------------
__global__ __launch_bounds__(256)
void scatter_kernel(const float* __restrict__ rel, const int* __restrict__ sub,
                    const int* __restrict__ obj) {
    const int e = blockIdx.x;
    const int tid = threadIdx.x;
    const int s = sub[e], o = obj[e];
    const float as = g_alpha[e] / (g_denom[s] + 1e-9f);
    const float ao = g_alpha[NE + e] / (g_denom[NB + o] + 1e-9f);

    const float4* r = (const float4*)(rel + (size_t)e * FD);
    float* ws = g_wsum + (size_t)s * FD;
    float* wo = g_wsum + ((size_t)NB + o) * FD;
    for (int i = tid; i < FD / 4; i += blockDim.x) {
        float4 v = r[i];
        int c = i * 4;
        atomicAdd(&ws[c + 0], as * v.x);
        atomicAdd(&ws[c + 1], as * v.y);
        atomicAdd(&ws[c + 2], as * v.z);
        atomicAdd(&ws[c + 3], as * v.w);
        atomicAdd(&wo[c + 0], ao * v.x);
        atomicAdd(&wo[c + 1], ao * v.y);
        atomicAdd(&wo[c + 2], ao * v.z);
        atomicAdd(&wo[c + 3], ao * v.w);
    }
}

// ---------------- acc init with biases ----------------
__global__ void biasinit_kernel(const float* __restrict__ b_box,
                                const float* __restrict__ b_sub,
                                const float* __restrict__ b_obj) {
    size_t idx = (size_t)blockIdx.x * blockDim.x + threadIdx.x;
    if (idx >= (size_t)NB * OD) return;
    int i = (int)(idx / OD);
    int n = (int)(idx % OD);
    g_acc[idx] = b_box[n] + g_salpha[i] * b_sub[n] + g_salpha[NB + i] * b_obj[n];
}

// ---------------- launch ----------------
static inline void split(const float* src, __nv_bfloat16* hi, __nv_bfloat16* lo, long n) {
    split_kernel<<<(int)((n / 4 + 255) / 256), 256>>>(src, hi, lo, n);
}

extern "C" void kernel_launch(void* const* d_in, const int* in_sizes, int n_in,
                              void* d_out, int out_size) {
    const float* box_feats = (const float*)d_in[0];
    const float* rel_feats = (const float*)d_in[1];
    const int*   edge_sub  = (const int*)d_in[2];
    const int*   edge_obj  = (const int*)d_in[3];
    const float* W_box  = (const float*)d_in[4];
    const float* b_box  = (const float*)d_in[5];
    const float* W_sub  = (const float*)d_in[6];
    const float* b_sub  = (const float*)d_in[7];
    const float* W_obj  = (const float*)d_in[8];
    const float* b_obj  = (const float*)d_in[9];
    const float* Wa_box = (const float*)d_in[10];
    const float* Wa_rel = (const float*)d_in[11];
    const float* b_a1   = (const float*)d_in[12];
    const float* Wa2    = (const float*)d_in[13];
    const float* b_a2   = (const float*)d_in[14];
    float* out = (float*)d_out;

    float *box_att, *rel_att, *acc;
    cudaGetSymbolAddress((void**)&box_att, g_box_att);
    cudaGetSymbolAddress((void**)&rel_att, g_rel_att);
    cudaGetSymbolAddress((void**)&acc, g_acc);
    float* wsum; cudaGetSymbolAddress((void**)&wsum, g_wsum);

    __nv_bfloat16 *relh, *rell, *boxh, *boxl, *wsh, *wsl;
    __nv_bfloat16 *Wabh, *Wabl, *Warh, *Warl, *Wbh, *Wbl, *Wsh, *Wsl, *Woh, *Wol;
    cudaGetSymbolAddress((void**)&relh, g_relh); cudaGetSymbolAddress((void**)&rell, g_rell);
    cudaGetSymbolAddress((void**)&boxh, g_boxh); cudaGetSymbolAddress((void**)&boxl, g_boxl);
    cudaGetSymbolAddress((void**)&wsh,  g_wsh);  cudaGetSymbolAddress((void**)&wsl,  g_wsl);
    cudaGetSymbolAddress((void**)&Wabh, g_Wabh); cudaGetSymbolAddress((void**)&Wabl, g_Wabl);
    cudaGetSymbolAddress((void**)&Warh, g_Warh); cudaGetSymbolAddress((void**)&Warl, g_Warl);
    cudaGetSymbolAddress((void**)&Wbh,  g_Wbh);  cudaGetSymbolAddress((void**)&Wbl,  g_Wbl);
    cudaGetSymbolAddress((void**)&Wsh,  g_Wsh);  cudaGetSymbolAddress((void**)&Wsl,  g_Wsl);
    cudaGetSymbolAddress((void**)&Woh,  g_Woh);  cudaGetSymbolAddress((void**)&Wol,  g_Wol);

    init_kernel<<<2048, 256>>>();

    // split inputs/weights into bf16 hi/lo
    split(box_feats, boxh, boxl, (long)NB * OD);
    split(rel_feats, relh, rell, (long)NE * FD);
    split(Wa_box, Wabh, Wabl, (long)OD * OD);
    split(Wa_rel, Warh, Warl, (long)FD * OD);
    split(W_box,  Wbh,  Wbl,  (long)OD * OD);
    split(W_sub,  Wsh,  Wsl,  (long)FD * OD);
    split(W_obj,  Woh,  Wol,  (long)FD * OD);

    // box_att = box_feats @ Wa_box
    mma_gemm<<<dim3(OD / 128, NB / 128), 256>>>(boxh, boxl, Wabh, Wabl, nullptr, box_att,
                                                NB, OD, OD, 0);
    // rel_att = rel_feats @ Wa_rel   (dominant)
    mma_gemm<<<dim3(OD / 128, NE / 128), 256>>>(relh, rell, Warh, Warl, nullptr, rel_att,
                                                NE, OD, FD, 0);

    logit_kernel<<<NE, 256>>>(edge_sub, edge_obj, b_a1, Wa2, b_a2);
    segmax_kernel<<<(NE + 255) / 256, 256>>>(edge_sub, edge_obj);
    expsum_kernel<<<(NE + 255) / 256, 256>>>(edge_sub, edge_obj);
    salpha_kernel<<<(2 * NB + 255) / 256, 256>>>();
    scatter_kernel<<<NE, 256>>>(rel_feats, edge_sub, edge_obj);

    // split wsum (both halves) into bf16 hi/lo
    split(wsum, wsh, wsl, 2L * NB * FD);

    biasinit_kernel<<<(int)(((size_t)NB * OD + 255) / 256), 256>>>(b_box, b_sub, b_obj);

    // acc += box_feats @ W_box ; acc += wsum_s @ W_sub ; out = relu(acc + wsum_o @ W_obj)
    mma_gemm<<<dim3(OD / 128, NB / 128), 256>>>(boxh, boxl, Wbh, Wbl, acc, acc,
                                                NB, OD, OD, 0);
    mma_gemm<<<dim3(OD / 128, NB / 128), 256>>>(wsh, wsl, Wsh, Wsl, acc, acc,
                                                NB, OD, FD, 0);
    mma_gemm<<<dim3(OD / 128, NB / 128), 256>>>(wsh + (size_t)NB * FD, wsl + (size_t)NB * FD,
                                                Woh, Wol, acc, out,
                                                NB, OD, FD, 1);
}